// round 6
// baseline (speedup 1.0000x reference)
#include <cuda_runtime.h>
#include <cuda_fp16.h>
#include <cstdint>

// ---------------- problem dims ----------------
#define B_ 8192
#define V_ 1024
#define E_ 640
#define H_ 640
#define L_ 2
#define D_ 512
#define J_ 640

// ---------------- GEMM smem layout ----------------
#define ROWB   80                    // bytes per smem row: 32 fp16 (64B) + 16B pad
#define TILEB  (128 * ROWB)          // one 128x32 fp16 tile = 10240 B
#define NSTAGE 4

// ================= low-level helpers (base sm_100 ISA only) =================
__device__ __forceinline__ uint32_t smem_to_u32(const void* p) {
    uint32_t a;
    asm("{ .reg .u64 t; cvta.to.shared.u64 t, %1; cvt.u32.u64 %0, t; }"
        : "=r"(a) : "l"(p));
    return a;
}
__device__ __forceinline__ void cp_async16(uint32_t saddr, const void* gptr) {
    asm volatile("cp.async.cg.shared.global [%0], [%1], 16;"
                 :: "r"(saddr), "l"(gptr));
}
__device__ __forceinline__ void cp_commit() {
    asm volatile("cp.async.commit_group;");
}
template <int N>
__device__ __forceinline__ void cp_wait() {
    asm volatile("cp.async.wait_group %0;" :: "n"(N));
}
__device__ __forceinline__ void ldsm_x4(uint32_t* r, uint32_t addr) {
    asm volatile("ldmatrix.sync.aligned.m8n8.x4.shared.b16 {%0,%1,%2,%3}, [%4];"
                 : "=r"(r[0]), "=r"(r[1]), "=r"(r[2]), "=r"(r[3]) : "r"(addr));
}
__device__ __forceinline__ void mma_fp16(float* c, const uint32_t* a,
                                         uint32_t b0, uint32_t b1) {
    asm volatile(
        "mma.sync.aligned.m16n8k16.row.col.f32.f16.f16.f32 "
        "{%0,%1,%2,%3}, {%4,%5,%6,%7}, {%8,%9}, {%0,%1,%2,%3};"
        : "+f"(c[0]), "+f"(c[1]), "+f"(c[2]), "+f"(c[3])
        : "r"(a[0]), "r"(a[1]), "r"(a[2]), "r"(a[3]), "r"(b0), "r"(b1));
}

// ================= scratch (no allocations allowed) =================
// single-pass fp16 operands (gate GEMMs; weights gate-interleaved)
__device__ __align__(16) __half g_xh[B_ * E_];
__device__ __align__(16) __half g_h0h[L_ * B_ * H_];
__device__ __align__(16) __half g_h1s[B_ * H_];                 // layer-0 h1 (single)
__device__ __align__(16) __half g_wih[L_ * 4 * H_ * H_];        // interleaved rows
__device__ __align__(16) __half g_whh[L_ * 4 * H_ * H_];        // interleaved rows
// split fp16 operands (joint + output GEMMs)
__device__ __align__(16) __half g_predhi[B_ * H_], g_predlo[B_ * H_];
__device__ __align__(16) __half g_enchi[B_ * D_],  g_enclo[B_ * D_];
__device__ __align__(16) __half g_zhi[B_ * J_],    g_zlo[B_ * J_];
__device__ __align__(16) __half g_wenchi[J_ * D_], g_wenclo[J_ * D_];
__device__ __align__(16) __half g_wpredhi[J_ * H_], g_wpredlo[J_ * H_];
__device__ __align__(16) __half g_wouthi[V_ * J_],  g_woutlo[V_ * J_];

__device__ __forceinline__ void split1h(float v, __half& h, __half& l) {
    h = __float2half_rn(v);
    l = __float2half_rn(v - __half2float(h));
}
__device__ __forceinline__ float sigmoidf_(float x) {
    return 1.0f / (1.0f + expf(-x));
}

// ================= fused prep kernel (all conversions in one launch) =========
// Exact segment sizes (in float4 units, all multiples of 256):
//   s0 gather x           : 1,310,720 f4 -> 5120 blocks
//   s1 h0 conv            : 2,621,440 f4 -> 10240
//   s2 w_ih perm conv     :   819,200 f4 -> 3200
//   s3 w_hh perm conv     :   819,200 f4 -> 3200
//   s4 enc split          : 1,048,576 f4 -> 4096
//   s5 w_enc split        :    81,920 f4 -> 320
//   s6 w_pred split       :   102,400 f4 -> 400
//   s7 w_out split        :   163,840 f4 -> 640
#define PB0 5120
#define PB1 15360
#define PB2 18560
#define PB3 21760
#define PB4 25856
#define PB5 26176
#define PB6 26576
#define PB7 27216

__device__ __forceinline__ void conv_one(float4 v, __half2* out, size_t i) {
    out[2 * i]     = __floats2half2_rn(v.x, v.y);
    out[2 * i + 1] = __floats2half2_rn(v.z, v.w);
}
__device__ __forceinline__ void split_one(float4 v, __half2* hi, __half2* lo, size_t i) {
    __half hx, lx, hy, ly, hz, lz, hw, lw;
    split1h(v.x, hx, lx); split1h(v.y, hy, ly);
    split1h(v.z, hz, lz); split1h(v.w, hw, lw);
    hi[2 * i]     = __halves2half2(hx, hy);
    hi[2 * i + 1] = __halves2half2(hz, hw);
    lo[2 * i]     = __halves2half2(lx, ly);
    lo[2 * i + 1] = __halves2half2(lz, lw);
}
// gate-interleaved weight permute: dst row c = src row (c&3)*H + (c>>2)
__device__ __forceinline__ void perm_conv(const float4* src, __half2* dst, int i) {
    const int PER_L = 4 * H_ * (H_ / 4);      // 409600 f4 per layer
    int l   = i / PER_L;
    int rem = i - l * PER_L;
    int row = rem / (H_ / 4);
    int kq  = rem - row * (H_ / 4);
    int srow = (row & 3) * H_ + (row >> 2);
    float4 v = src[(size_t)l * PER_L + (size_t)srow * (H_ / 4) + kq];
    conv_one(v, dst, i);
}

__global__ void prep_all(const int* __restrict__ ids, const float4* __restrict__ emb,
                         const float4* __restrict__ h0,
                         const float4* __restrict__ w_ih, const float4* __restrict__ w_hh,
                         const float4* __restrict__ enc, const float4* __restrict__ w_enc,
                         const float4* __restrict__ w_pred, const float4* __restrict__ w_out) {
    const int b = blockIdx.x;
    const int tid = threadIdx.x;
    if (b < PB0) {
        int i = b * 256 + tid;                       // over B_*(E_/4)
        int bb = i / (E_ / 4);
        int q  = i - bb * (E_ / 4);
        float4 v = emb[(size_t)ids[bb] * (E_ / 4) + q];
        conv_one(v, (__half2*)g_xh, i);
    } else if (b < PB1) {
        int i = (b - PB0) * 256 + tid;
        conv_one(h0[i], (__half2*)g_h0h, i);
    } else if (b < PB2) {
        int i = (b - PB1) * 256 + tid;
        perm_conv(w_ih, (__half2*)g_wih, i);
    } else if (b < PB3) {
        int i = (b - PB2) * 256 + tid;
        perm_conv(w_hh, (__half2*)g_whh, i);
    } else if (b < PB4) {
        int i = (b - PB3) * 256 + tid;
        split_one(enc[i], (__half2*)g_enchi, (__half2*)g_enclo, i);
    } else if (b < PB5) {
        int i = (b - PB4) * 256 + tid;
        split_one(w_enc[i], (__half2*)g_wenchi, (__half2*)g_wenclo, i);
    } else if (b < PB6) {
        int i = (b - PB5) * 256 + tid;
        split_one(w_pred[i], (__half2*)g_wpredhi, (__half2*)g_wpredlo, i);
    } else if (b < PB7) {
        int i = (b - PB6) * 256 + tid;
        split_one(w_out[i], (__half2*)g_wouthi, (__half2*)g_woutlo, i);
    }
}

// ================= fp16 HMMA GEMM =================
// SPLIT=0: single-pass fp16 (1 MMA per pair); SPLIT=1: 3-MMA hi/lo split.
// CELL=1: gate GEMM with interleaved columns; epilogue performs the LSTM cell
//   (lane-pair shuffle to gather i,f,g,o), writing h1f/c1f and fp16 h
//   (single to hs, or hi/lo split to hhi/hlo). Biases indexed with the
//   de-interleaving permutation.
// CTA tile 128x128, 512 threads = 16 warps (4x4), warp tile 32x32,
// K chunks of 32, 4-stage cp.async pipeline.
template <int SPLIT, int CELL>
__global__ void __launch_bounds__(512, 1)
gemm_hmma(const __half* __restrict__ A1h, const __half* __restrict__ A1l,
          const __half* __restrict__ W1h, const __half* __restrict__ W1l, int K1,
          const __half* __restrict__ A2h, const __half* __restrict__ A2l,
          const __half* __restrict__ W2h, const __half* __restrict__ W2l, int K2,
          const float* __restrict__ b1, const float* __restrict__ b2,
          float* __restrict__ Cf,
          __half* __restrict__ Chi, __half* __restrict__ Clo,
          int ldc, int relu,
          const float* __restrict__ c0p, float* __restrict__ h1f,
          float* __restrict__ c1f,
          __half* __restrict__ hs, __half* __restrict__ hhi,
          __half* __restrict__ hlo)
{
    constexpr int TILES  = SPLIT ? 4 : 2;
    constexpr int WOFF   = SPLIT ? 2 : 1;         // tile index of W_hi in stage
    constexpr int STAGEB = TILES * TILEB;

    extern __shared__ char smem[];
    const uint32_t sbase = smem_to_u32(smem);
    const int tid = threadIdx.x;
    const int wid = tid >> 5;
    const int lid = tid & 31;
    const int m0  = blockIdx.y * 128;
    const int n0  = blockIdx.x * 128;
    const int wm  = (wid & 3) * 32;     // warp M offset in tile
    const int wn  = (wid >> 2) * 32;    // warp N offset in tile

    float acc[2][4][4];
    #pragma unroll
    for (int i = 0; i < 2; i++)
        #pragma unroll
        for (int j = 0; j < 4; j++)
            #pragma unroll
            for (int k = 0; k < 4; k++) acc[i][j][k] = 0.f;

    const int nch1 = K1 / 32;
    const int nch  = nch1 + K2 / 32;

    const int lrow = tid >> 2;          // 0..127
    const int lcg  = tid & 3;           // 16B column group

    auto load_chunk = [&](int c) {
        const __half* srcs[4];
        int kbase, Kc;
        if (c < nch1) {
            kbase = c * 32; Kc = K1;
            if (SPLIT) { srcs[0] = A1h; srcs[1] = A1l; srcs[2] = W1h; srcs[3] = W1l; }
            else       { srcs[0] = A1h; srcs[1] = W1h; }
        } else {
            kbase = (c - nch1) * 32; Kc = K2;
            if (SPLIT) { srcs[0] = A2h; srcs[1] = A2l; srcs[2] = W2h; srcs[3] = W2l; }
            else       { srcs[0] = A2h; srcs[1] = W2h; }
        }
        const uint32_t st = sbase + (uint32_t)(c & (NSTAGE - 1)) * STAGEB;
        #pragma unroll
        for (int m = 0; m < TILES; ++m) {
            const int rb = (m < WOFF) ? m0 : n0;
            const void* g = srcs[m] + (size_t)(rb + lrow) * Kc + kbase + lcg * 8;
            uint32_t s = st + m * TILEB + lrow * ROWB + lcg * 16;
            cp_async16(s, g);
        }
        cp_commit();
    };

    load_chunk(0);
    load_chunk(1);
    load_chunk(2);

    for (int c = 0; c < nch; ++c) {
        cp_wait<2>();
        __syncthreads();
        if (c + 3 < nch) load_chunk(c + 3);

        const uint32_t st = sbase + (uint32_t)(c & (NSTAGE - 1)) * STAGEB;
        #pragma unroll
        for (int ks = 0; ks < 2; ++ks) {
            const int kb = ks * 32;
            uint32_t ah[2][4], al[2][4];
            #pragma unroll
            for (int mf = 0; mf < 2; ++mf) {
                uint32_t addr = st + (wm + mf * 16 + (lid & 15)) * ROWB
                              + kb + ((lid >> 4) * 16);
                ldsm_x4(ah[mf], addr);
                if (SPLIT) ldsm_x4(al[mf], addr + TILEB);
            }
            uint32_t bh[2][4], bl[2][4];
            #pragma unroll
            for (int ng = 0; ng < 2; ++ng) {
                int nrow = wn + ng * 16 + ((lid >> 4) << 3) + (lid & 7);
                int kof  = ((lid >> 3) & 1) * 16;
                uint32_t addr = st + WOFF * TILEB + nrow * ROWB + kb + kof;
                ldsm_x4(bh[ng], addr);
                if (SPLIT) ldsm_x4(bl[ng], addr + TILEB);
            }
            #pragma unroll
            for (int mf = 0; mf < 2; ++mf)
                #pragma unroll
                for (int nf = 0; nf < 4; ++nf) {
                    const int ng = nf >> 1, hf = (nf & 1) * 2;
                    mma_fp16(acc[mf][nf], ah[mf], bh[ng][hf], bh[ng][hf + 1]);
                    if (SPLIT) {
                        mma_fp16(acc[mf][nf], ah[mf], bl[ng][hf], bl[ng][hf + 1]);
                        mma_fp16(acc[mf][nf], al[mf], bh[ng][hf], bh[ng][hf + 1]);
                    }
                }
        }
        __syncthreads();
    }

    // ---- epilogue ----
    const int g = lid >> 2;
    const int t = lid & 3;

    if (CELL) {
        // columns are gate-interleaved: col = 4*unit + gate
        const bool even = ((t & 1) == 0);
        #pragma unroll
        for (int nf = 0; nf < 4; ++nf) {
            const int col   = n0 + wn + nf * 8 + t * 2;
            const int gate0 = col & 3;                 // 0 (even lanes) or 2 (odd)
            const int u     = col >> 2;                // hidden unit
            const float bb0 = b1[gate0 * H_ + u] + b2[gate0 * H_ + u];
            const float bb1 = b1[(gate0 + 1) * H_ + u] + b2[(gate0 + 1) * H_ + u];
            #pragma unroll
            for (int mf = 0; mf < 2; ++mf) {
                #pragma unroll
                for (int rr = 0; rr < 2; ++rr) {
                    const int r = m0 + wm + mf * 16 + g + rr * 8;
                    float v0 = acc[mf][nf][rr * 2 + 0] + bb0;
                    float v1 = acc[mf][nf][rr * 2 + 1] + bb1;
                    float p0 = __shfl_xor_sync(0xffffffffu, v0, 1);
                    float p1 = __shfl_xor_sync(0xffffffffu, v1, 1);
                    if (even) {
                        // self: i,f ; partner: g,o
                        float ig = sigmoidf_(v0);
                        float fg = sigmoidf_(v1);
                        float gg = tanhf(p0);
                        float og = sigmoidf_(p1);
                        size_t o = (size_t)r * H_ + u;
                        float cc = fg * c0p[o] + ig * gg;
                        float hh = og * tanhf(cc);
                        c1f[o] = cc;
                        h1f[o] = hh;
                        if (hs) {
                            hs[o] = __float2half_rn(hh);
                        } else {
                            __half sh, sl;
                            split1h(hh, sh, sl);
                            hhi[o] = sh;
                            hlo[o] = sl;
                        }
                    }
                }
            }
        }
        return;
    }

    #pragma unroll
    for (int nf = 0; nf < 4; ++nf) {
        const int col = n0 + wn + nf * 8 + t * 2;
        float bb0 = b1[col],     bb1 = b1[col + 1];
        if (b2) { bb0 += b2[col]; bb1 += b2[col + 1]; }
        #pragma unroll
        for (int mf = 0; mf < 2; ++mf) {
            const int r0 = m0 + wm + mf * 16 + g;
            const int r1 = r0 + 8;
            float v00 = acc[mf][nf][0] + bb0;
            float v01 = acc[mf][nf][1] + bb1;
            float v10 = acc[mf][nf][2] + bb0;
            float v11 = acc[mf][nf][3] + bb1;
            if (relu) {
                v00 = fmaxf(v00, 0.f); v01 = fmaxf(v01, 0.f);
                v10 = fmaxf(v10, 0.f); v11 = fmaxf(v11, 0.f);
            }
            if (Chi) {
                __half h0b, l0b, h1b, l1b;
                split1h(v00, h0b, l0b); split1h(v01, h1b, l1b);
                *reinterpret_cast<__half2*>(Chi + (size_t)r0 * ldc + col) = __halves2half2(h0b, h1b);
                *reinterpret_cast<__half2*>(Clo + (size_t)r0 * ldc + col) = __halves2half2(l0b, l1b);
                split1h(v10, h0b, l0b); split1h(v11, h1b, l1b);
                *reinterpret_cast<__half2*>(Chi + (size_t)r1 * ldc + col) = __halves2half2(h0b, h1b);
                *reinterpret_cast<__half2*>(Clo + (size_t)r1 * ldc + col) = __halves2half2(l0b, l1b);
            } else {
                *reinterpret_cast<float2*>(Cf + (size_t)r0 * ldc + col) = make_float2(v00, v01);
                *reinterpret_cast<float2*>(Cf + (size_t)r1 * ldc + col) = make_float2(v10, v11);
            }
        }
    }
}

// ================= launch =================
extern "C" void kernel_launch(void* const* d_in, const int* in_sizes, int n_in,
                              void* d_out, int out_size) {
    const int*   ids    = (const int*)  d_in[0];
    const float* h0     = (const float*)d_in[1];
    const float* c0     = (const float*)d_in[2];
    const float* enc    = (const float*)d_in[3];
    const float* emb    = (const float*)d_in[4];
    const float* w_ih   = (const float*)d_in[5];
    const float* w_hh   = (const float*)d_in[6];
    const float* b_ih   = (const float*)d_in[7];
    const float* b_hh   = (const float*)d_in[8];
    const float* w_enc  = (const float*)d_in[9];
    const float* b_enc  = (const float*)d_in[10];
    const float* w_pred = (const float*)d_in[11];
    const float* b_pred = (const float*)d_in[12];
    const float* w_out  = (const float*)d_in[13];
    const float* b_out  = (const float*)d_in[14];

    float* out    = (float*)d_out;
    float* logits = out;                                 // (B, V)
    float* h1f    = out + (size_t)B_ * V_;               // (L, B, H)
    float* c1f    = h1f + (size_t)L_ * B_ * H_;          // (L, B, H)

    __half *xh, *h0h, *h1s;
    __half *wih, *whh;
    __half *predhi, *predlo, *enchi, *enclo, *zhi, *zlo;
    __half *wenchi, *wenclo, *wpredhi, *wpredlo, *wouthi, *woutlo;
    cudaGetSymbolAddress((void**)&xh,  g_xh);
    cudaGetSymbolAddress((void**)&h0h, g_h0h);
    cudaGetSymbolAddress((void**)&h1s, g_h1s);
    cudaGetSymbolAddress((void**)&wih, g_wih);
    cudaGetSymbolAddress((void**)&whh, g_whh);
    cudaGetSymbolAddress((void**)&predhi, g_predhi); cudaGetSymbolAddress((void**)&predlo, g_predlo);
    cudaGetSymbolAddress((void**)&enchi, g_enchi);   cudaGetSymbolAddress((void**)&enclo, g_enclo);
    cudaGetSymbolAddress((void**)&zhi, g_zhi);       cudaGetSymbolAddress((void**)&zlo, g_zlo);
    cudaGetSymbolAddress((void**)&wenchi, g_wenchi); cudaGetSymbolAddress((void**)&wenclo, g_wenclo);
    cudaGetSymbolAddress((void**)&wpredhi, g_wpredhi); cudaGetSymbolAddress((void**)&wpredlo, g_wpredlo);
    cudaGetSymbolAddress((void**)&wouthi, g_wouthi); cudaGetSymbolAddress((void**)&woutlo, g_woutlo);

    const int SMEM0 = NSTAGE * 2 * TILEB;   // 81920
    const int SMEM1 = NSTAGE * 4 * TILEB;   // 163840
    cudaFuncSetAttribute((const void*)gemm_hmma<0, 1>,
                         cudaFuncAttributeMaxDynamicSharedMemorySize, SMEM0);
    cudaFuncSetAttribute((const void*)gemm_hmma<1, 0>,
                         cudaFuncAttributeMaxDynamicSharedMemorySize, SMEM1);

    // ---- fused prep (gather + all conversions + gate-interleave permute) ----
    prep_all<<<PB7, 256>>>(ids, (const float4*)emb, (const float4*)h0,
                           (const float4*)w_ih, (const float4*)w_hh,
                           (const float4*)enc, (const float4*)w_enc,
                           (const float4*)w_pred, (const float4*)w_out);

    const int WIH = 4 * H_ * H_;     // per-layer w_ih/w_hh elems
    const int BH  = B_ * H_;         // per-layer h slice elems

    dim3 blk(512);
    dim3 grdG(4 * H_ / 128, B_ / 128);   // 20 x 64

    // ---- layer 0: gates GEMM + fused cell -> h1[0], c1[0], h1s (fp16) ----
    gemm_hmma<0, 1><<<grdG, blk, SMEM0>>>(
        xh, nullptr, wih, nullptr, H_,
        h0h, nullptr, whh, nullptr, H_,
        b_ih, b_hh, nullptr, nullptr, nullptr, 0, 0,
        c0, h1f, c1f, h1s, nullptr, nullptr);

    // ---- layer 1: gates GEMM + fused cell -> h1[1], c1[1], pred hi/lo ----
    gemm_hmma<0, 1><<<grdG, blk, SMEM0>>>(
        h1s, nullptr, wih + WIH, nullptr, H_,
        h0h + BH, nullptr, whh + WIH, nullptr, H_,
        b_ih + 4 * H_, b_hh + 4 * H_, nullptr, nullptr, nullptr, 0, 0,
        c0 + BH, h1f + BH, c1f + BH, nullptr, predhi, predlo);

    // ---- joint: relu(enc*w_enc^T + pred*w_pred^T + b) -> z hi/lo (split) ----
    dim3 grdJ(J_ / 128, B_ / 128);       // 5 x 64
    gemm_hmma<1, 0><<<grdJ, blk, SMEM1>>>(
        enchi, enclo, wenchi, wenclo, D_,
        predhi, predlo, wpredhi, wpredlo, H_,
        b_enc, b_pred, nullptr, zhi, zlo, J_, 1,
        nullptr, nullptr, nullptr, nullptr, nullptr, nullptr);

    // ---- logits = z*w_out^T + b_out (split) ----
    dim3 grdO(V_ / 128, B_ / 128);       // 8 x 64
    gemm_hmma<1, 0><<<grdO, blk, SMEM1>>>(
        zhi, zlo, wouthi, woutlo, J_,
        nullptr, nullptr, nullptr, nullptr, 0,
        b_out, nullptr, logits, nullptr, nullptr, V_, 0,
        nullptr, nullptr, nullptr, nullptr, nullptr, nullptr);
}

// round 7
// speedup vs baseline: 1.0016x; 1.0016x over previous
#include <cuda_runtime.h>
#include <cuda_fp16.h>
#include <cstdint>

// ---------------- problem dims ----------------
#define B_ 8192
#define V_ 1024
#define E_ 640
#define H_ 640
#define L_ 2
#define D_ 512
#define J_ 640

// ---------------- GEMM smem layout ----------------
#define ROWB   80                    // bytes per smem row: 32 fp16 (64B) + 16B pad
#define TILEB  (128 * ROWB)          // one 128x32 fp16 tile = 10240 B
#define NSTAGE 4

// ================= low-level helpers (base sm_100 ISA only) =================
__device__ __forceinline__ uint32_t smem_to_u32(const void* p) {
    uint32_t a;
    asm("{ .reg .u64 t; cvta.to.shared.u64 t, %1; cvt.u32.u64 %0, t; }"
        : "=r"(a) : "l"(p));
    return a;
}
__device__ __forceinline__ void cp_async16(uint32_t saddr, const void* gptr) {
    asm volatile("cp.async.cg.shared.global [%0], [%1], 16;"
                 :: "r"(saddr), "l"(gptr));
}
__device__ __forceinline__ void cp_commit() {
    asm volatile("cp.async.commit_group;");
}
template <int N>
__device__ __forceinline__ void cp_wait() {
    asm volatile("cp.async.wait_group %0;" :: "n"(N));
}
__device__ __forceinline__ void ldsm_x4(uint32_t* r, uint32_t addr) {
    asm volatile("ldmatrix.sync.aligned.m8n8.x4.shared.b16 {%0,%1,%2,%3}, [%4];"
                 : "=r"(r[0]), "=r"(r[1]), "=r"(r[2]), "=r"(r[3]) : "r"(addr));
}
__device__ __forceinline__ void mma_fp16(float* c, const uint32_t* a,
                                         uint32_t b0, uint32_t b1) {
    asm volatile(
        "mma.sync.aligned.m16n8k16.row.col.f32.f16.f16.f32 "
        "{%0,%1,%2,%3}, {%4,%5,%6,%7}, {%8,%9}, {%0,%1,%2,%3};"
        : "+f"(c[0]), "+f"(c[1]), "+f"(c[2]), "+f"(c[3])
        : "r"(a[0]), "r"(a[1]), "r"(a[2]), "r"(a[3]), "r"(b0), "r"(b1));
}

// ================= scratch (no allocations allowed) =================
// single-pass fp16 operands (gate GEMMs; weights gate-interleaved)
__device__ __align__(16) __half g_xh[B_ * E_];
__device__ __align__(16) __half g_h0h[L_ * B_ * H_];
__device__ __align__(16) __half g_h1s[B_ * H_];                 // layer-0 h1 (single)
__device__ __align__(16) __half g_wih[L_ * 4 * H_ * H_];        // interleaved rows
__device__ __align__(16) __half g_whh[L_ * 4 * H_ * H_];        // interleaved rows
// split fp16 operands (joint + output GEMMs)
__device__ __align__(16) __half g_predhi[B_ * H_], g_predlo[B_ * H_];
__device__ __align__(16) __half g_enchi[B_ * D_],  g_enclo[B_ * D_];
__device__ __align__(16) __half g_zhi[B_ * J_],    g_zlo[B_ * J_];
__device__ __align__(16) __half g_wenchi[J_ * D_], g_wenclo[J_ * D_];
__device__ __align__(16) __half g_wpredhi[J_ * H_], g_wpredlo[J_ * H_];
__device__ __align__(16) __half g_wouthi[V_ * J_],  g_woutlo[V_ * J_];

__device__ __forceinline__ void split1h(float v, __half& h, __half& l) {
    h = __float2half_rn(v);
    l = __float2half_rn(v - __half2float(h));
}
__device__ __forceinline__ float sigmoidf_(float x) {
    return 1.0f / (1.0f + expf(-x));
}

// ================= fused prep kernel (all conversions in one launch) =========
// Exact segment sizes (in float4 units, all multiples of 256):
//   s0 gather x           : 1,310,720 f4 -> 5120 blocks
//   s1 h0 conv            : 2,621,440 f4 -> 10240
//   s2 w_ih perm conv     :   819,200 f4 -> 3200
//   s3 w_hh perm conv     :   819,200 f4 -> 3200
//   s4 enc split          : 1,048,576 f4 -> 4096
//   s5 w_enc split        :    81,920 f4 -> 320
//   s6 w_pred split       :   102,400 f4 -> 400
//   s7 w_out split        :   163,840 f4 -> 640
#define PB0 5120
#define PB1 15360
#define PB2 18560
#define PB3 21760
#define PB4 25856
#define PB5 26176
#define PB6 26576
#define PB7 27216

__device__ __forceinline__ void conv_one(float4 v, __half2* out, size_t i) {
    out[2 * i]     = __floats2half2_rn(v.x, v.y);
    out[2 * i + 1] = __floats2half2_rn(v.z, v.w);
}
__device__ __forceinline__ void split_one(float4 v, __half2* hi, __half2* lo, size_t i) {
    __half hx, lx, hy, ly, hz, lz, hw, lw;
    split1h(v.x, hx, lx); split1h(v.y, hy, ly);
    split1h(v.z, hz, lz); split1h(v.w, hw, lw);
    hi[2 * i]     = __halves2half2(hx, hy);
    hi[2 * i + 1] = __halves2half2(hz, hw);
    lo[2 * i]     = __halves2half2(lx, ly);
    lo[2 * i + 1] = __halves2half2(lz, lw);
}
// gate-interleaved weight permute: dst row c = src row (c&3)*H + (c>>2)
__device__ __forceinline__ void perm_conv(const float4* src, __half2* dst, int i) {
    const int PER_L = 4 * H_ * (H_ / 4);      // 409600 f4 per layer
    int l   = i / PER_L;
    int rem = i - l * PER_L;
    int row = rem / (H_ / 4);
    int kq  = rem - row * (H_ / 4);
    int srow = (row & 3) * H_ + (row >> 2);
    float4 v = src[(size_t)l * PER_L + (size_t)srow * (H_ / 4) + kq];
    conv_one(v, dst, i);
}

__global__ void prep_all(const int* __restrict__ ids, const float4* __restrict__ emb,
                         const float4* __restrict__ h0,
                         const float4* __restrict__ w_ih, const float4* __restrict__ w_hh,
                         const float4* __restrict__ enc, const float4* __restrict__ w_enc,
                         const float4* __restrict__ w_pred, const float4* __restrict__ w_out) {
    const int b = blockIdx.x;
    const int tid = threadIdx.x;
    if (b < PB0) {
        int i = b * 256 + tid;                       // over B_*(E_/4)
        int bb = i / (E_ / 4);
        int q  = i - bb * (E_ / 4);
        float4 v = emb[(size_t)ids[bb] * (E_ / 4) + q];
        conv_one(v, (__half2*)g_xh, i);
    } else if (b < PB1) {
        int i = (b - PB0) * 256 + tid;
        conv_one(h0[i], (__half2*)g_h0h, i);
    } else if (b < PB2) {
        int i = (b - PB1) * 256 + tid;
        perm_conv(w_ih, (__half2*)g_wih, i);
    } else if (b < PB3) {
        int i = (b - PB2) * 256 + tid;
        perm_conv(w_hh, (__half2*)g_whh, i);
    } else if (b < PB4) {
        int i = (b - PB3) * 256 + tid;
        split_one(enc[i], (__half2*)g_enchi, (__half2*)g_enclo, i);
    } else if (b < PB5) {
        int i = (b - PB4) * 256 + tid;
        split_one(w_enc[i], (__half2*)g_wenchi, (__half2*)g_wenclo, i);
    } else if (b < PB6) {
        int i = (b - PB5) * 256 + tid;
        split_one(w_pred[i], (__half2*)g_wpredhi, (__half2*)g_wpredlo, i);
    } else if (b < PB7) {
        int i = (b - PB6) * 256 + tid;
        split_one(w_out[i], (__half2*)g_wouthi, (__half2*)g_woutlo, i);
    }
}

// ================= fp16 HMMA GEMM =================
// SPLIT=0: single-pass fp16 (1 MMA per pair); SPLIT=1: 3-MMA hi/lo split.
// CELL=1: gate GEMM with interleaved columns; epilogue performs the LSTM cell
//   (lane-pair shuffle to gather i,f,g,o), writing h1f/c1f and fp16 h
//   (single to hs, or hi/lo split to hhi/hlo). Biases indexed with the
//   de-interleaving permutation.
// CTA tile 128x128, 512 threads = 16 warps (4x4), warp tile 32x32,
// K chunks of 32, 4-stage cp.async pipeline.
template <int SPLIT, int CELL>
__global__ void __launch_bounds__(512, 1)
gemm_hmma(const __half* __restrict__ A1h, const __half* __restrict__ A1l,
          const __half* __restrict__ W1h, const __half* __restrict__ W1l, int K1,
          const __half* __restrict__ A2h, const __half* __restrict__ A2l,
          const __half* __restrict__ W2h, const __half* __restrict__ W2l, int K2,
          const float* __restrict__ b1, const float* __restrict__ b2,
          float* __restrict__ Cf,
          __half* __restrict__ Chi, __half* __restrict__ Clo,
          int ldc, int relu,
          const float* __restrict__ c0p, float* __restrict__ h1f,
          float* __restrict__ c1f,
          __half* __restrict__ hs, __half* __restrict__ hhi,
          __half* __restrict__ hlo)
{
    constexpr int TILES  = SPLIT ? 4 : 2;
    constexpr int WOFF   = SPLIT ? 2 : 1;         // tile index of W_hi in stage
    constexpr int STAGEB = TILES * TILEB;

    extern __shared__ char smem[];
    const uint32_t sbase = smem_to_u32(smem);
    const int tid = threadIdx.x;
    const int wid = tid >> 5;
    const int lid = tid & 31;
    const int m0  = blockIdx.y * 128;
    const int n0  = blockIdx.x * 128;
    const int wm  = (wid & 3) * 32;     // warp M offset in tile
    const int wn  = (wid >> 2) * 32;    // warp N offset in tile

    float acc[2][4][4];
    #pragma unroll
    for (int i = 0; i < 2; i++)
        #pragma unroll
        for (int j = 0; j < 4; j++)
            #pragma unroll
            for (int k = 0; k < 4; k++) acc[i][j][k] = 0.f;

    const int nch1 = K1 / 32;
    const int nch  = nch1 + K2 / 32;

    const int lrow = tid >> 2;          // 0..127
    const int lcg  = tid & 3;           // 16B column group

    auto load_chunk = [&](int c) {
        const __half* srcs[4];
        int kbase, Kc;
        if (c < nch1) {
            kbase = c * 32; Kc = K1;
            if (SPLIT) { srcs[0] = A1h; srcs[1] = A1l; srcs[2] = W1h; srcs[3] = W1l; }
            else       { srcs[0] = A1h; srcs[1] = W1h; }
        } else {
            kbase = (c - nch1) * 32; Kc = K2;
            if (SPLIT) { srcs[0] = A2h; srcs[1] = A2l; srcs[2] = W2h; srcs[3] = W2l; }
            else       { srcs[0] = A2h; srcs[1] = W2h; }
        }
        const uint32_t st = sbase + (uint32_t)(c & (NSTAGE - 1)) * STAGEB;
        #pragma unroll
        for (int m = 0; m < TILES; ++m) {
            const int rb = (m < WOFF) ? m0 : n0;
            const void* g = srcs[m] + (size_t)(rb + lrow) * Kc + kbase + lcg * 8;
            uint32_t s = st + m * TILEB + lrow * ROWB + lcg * 16;
            cp_async16(s, g);
        }
        cp_commit();
    };

    load_chunk(0);
    load_chunk(1);
    load_chunk(2);

    for (int c = 0; c < nch; ++c) {
        cp_wait<2>();
        __syncthreads();
        if (c + 3 < nch) load_chunk(c + 3);

        const uint32_t st = sbase + (uint32_t)(c & (NSTAGE - 1)) * STAGEB;
        #pragma unroll
        for (int ks = 0; ks < 2; ++ks) {
            const int kb = ks * 32;
            uint32_t ah[2][4], al[2][4];
            #pragma unroll
            for (int mf = 0; mf < 2; ++mf) {
                uint32_t addr = st + (wm + mf * 16 + (lid & 15)) * ROWB
                              + kb + ((lid >> 4) * 16);
                ldsm_x4(ah[mf], addr);
                if (SPLIT) ldsm_x4(al[mf], addr + TILEB);
            }
            uint32_t bh[2][4], bl[2][4];
            #pragma unroll
            for (int ng = 0; ng < 2; ++ng) {
                int nrow = wn + ng * 16 + ((lid >> 4) << 3) + (lid & 7);
                int kof  = ((lid >> 3) & 1) * 16;
                uint32_t addr = st + WOFF * TILEB + nrow * ROWB + kb + kof;
                ldsm_x4(bh[ng], addr);
                if (SPLIT) ldsm_x4(bl[ng], addr + TILEB);
            }
            #pragma unroll
            for (int mf = 0; mf < 2; ++mf)
                #pragma unroll
                for (int nf = 0; nf < 4; ++nf) {
                    const int ng = nf >> 1, hf = (nf & 1) * 2;
                    mma_fp16(acc[mf][nf], ah[mf], bh[ng][hf], bh[ng][hf + 1]);
                    if (SPLIT) {
                        mma_fp16(acc[mf][nf], ah[mf], bl[ng][hf], bl[ng][hf + 1]);
                        mma_fp16(acc[mf][nf], al[mf], bh[ng][hf], bh[ng][hf + 1]);
                    }
                }
        }
        __syncthreads();
    }

    // ---- epilogue ----
    const int g = lid >> 2;
    const int t = lid & 3;

    if (CELL) {
        // columns are gate-interleaved: col = 4*unit + gate
        const bool even = ((t & 1) == 0);
        #pragma unroll
        for (int nf = 0; nf < 4; ++nf) {
            const int col   = n0 + wn + nf * 8 + t * 2;
            const int gate0 = col & 3;                 // 0 (even lanes) or 2 (odd)
            const int u     = col >> 2;                // hidden unit
            const float bb0 = b1[gate0 * H_ + u] + b2[gate0 * H_ + u];
            const float bb1 = b1[(gate0 + 1) * H_ + u] + b2[(gate0 + 1) * H_ + u];
            #pragma unroll
            for (int mf = 0; mf < 2; ++mf) {
                #pragma unroll
                for (int rr = 0; rr < 2; ++rr) {
                    const int r = m0 + wm + mf * 16 + g + rr * 8;
                    float v0 = acc[mf][nf][rr * 2 + 0] + bb0;
                    float v1 = acc[mf][nf][rr * 2 + 1] + bb1;
                    float p0 = __shfl_xor_sync(0xffffffffu, v0, 1);
                    float p1 = __shfl_xor_sync(0xffffffffu, v1, 1);
                    if (even) {
                        // self: i,f ; partner: g,o
                        float ig = sigmoidf_(v0);
                        float fg = sigmoidf_(v1);
                        float gg = tanhf(p0);
                        float og = sigmoidf_(p1);
                        size_t o = (size_t)r * H_ + u;
                        float cc = fg * c0p[o] + ig * gg;
                        float hh = og * tanhf(cc);
                        c1f[o] = cc;
                        h1f[o] = hh;
                        if (hs) {
                            hs[o] = __float2half_rn(hh);
                        } else {
                            __half sh, sl;
                            split1h(hh, sh, sl);
                            hhi[o] = sh;
                            hlo[o] = sl;
                        }
                    }
                }
            }
        }
        return;
    }

    #pragma unroll
    for (int nf = 0; nf < 4; ++nf) {
        const int col = n0 + wn + nf * 8 + t * 2;
        float bb0 = b1[col],     bb1 = b1[col + 1];
        if (b2) { bb0 += b2[col]; bb1 += b2[col + 1]; }
        #pragma unroll
        for (int mf = 0; mf < 2; ++mf) {
            const int r0 = m0 + wm + mf * 16 + g;
            const int r1 = r0 + 8;
            float v00 = acc[mf][nf][0] + bb0;
            float v01 = acc[mf][nf][1] + bb1;
            float v10 = acc[mf][nf][2] + bb0;
            float v11 = acc[mf][nf][3] + bb1;
            if (relu) {
                v00 = fmaxf(v00, 0.f); v01 = fmaxf(v01, 0.f);
                v10 = fmaxf(v10, 0.f); v11 = fmaxf(v11, 0.f);
            }
            if (Chi) {
                __half h0b, l0b, h1b, l1b;
                split1h(v00, h0b, l0b); split1h(v01, h1b, l1b);
                *reinterpret_cast<__half2*>(Chi + (size_t)r0 * ldc + col) = __halves2half2(h0b, h1b);
                *reinterpret_cast<__half2*>(Clo + (size_t)r0 * ldc + col) = __halves2half2(l0b, l1b);
                split1h(v10, h0b, l0b); split1h(v11, h1b, l1b);
                *reinterpret_cast<__half2*>(Chi + (size_t)r1 * ldc + col) = __halves2half2(h0b, h1b);
                *reinterpret_cast<__half2*>(Clo + (size_t)r1 * ldc + col) = __halves2half2(l0b, l1b);
            } else {
                *reinterpret_cast<float2*>(Cf + (size_t)r0 * ldc + col) = make_float2(v00, v01);
                *reinterpret_cast<float2*>(Cf + (size_t)r1 * ldc + col) = make_float2(v10, v11);
            }
        }
    }
}

// ================= launch =================
extern "C" void kernel_launch(void* const* d_in, const int* in_sizes, int n_in,
                              void* d_out, int out_size) {
    const int*   ids    = (const int*)  d_in[0];
    const float* h0     = (const float*)d_in[1];
    const float* c0     = (const float*)d_in[2];
    const float* enc    = (const float*)d_in[3];
    const float* emb    = (const float*)d_in[4];
    const float* w_ih   = (const float*)d_in[5];
    const float* w_hh   = (const float*)d_in[6];
    const float* b_ih   = (const float*)d_in[7];
    const float* b_hh   = (const float*)d_in[8];
    const float* w_enc  = (const float*)d_in[9];
    const float* b_enc  = (const float*)d_in[10];
    const float* w_pred = (const float*)d_in[11];
    const float* b_pred = (const float*)d_in[12];
    const float* w_out  = (const float*)d_in[13];
    const float* b_out  = (const float*)d_in[14];

    float* out    = (float*)d_out;
    float* logits = out;                                 // (B, V)
    float* h1f    = out + (size_t)B_ * V_;               // (L, B, H)
    float* c1f    = h1f + (size_t)L_ * B_ * H_;          // (L, B, H)

    __half *xh, *h0h, *h1s;
    __half *wih, *whh;
    __half *predhi, *predlo, *enchi, *enclo, *zhi, *zlo;
    __half *wenchi, *wenclo, *wpredhi, *wpredlo, *wouthi, *woutlo;
    cudaGetSymbolAddress((void**)&xh,  g_xh);
    cudaGetSymbolAddress((void**)&h0h, g_h0h);
    cudaGetSymbolAddress((void**)&h1s, g_h1s);
    cudaGetSymbolAddress((void**)&wih, g_wih);
    cudaGetSymbolAddress((void**)&whh, g_whh);
    cudaGetSymbolAddress((void**)&predhi, g_predhi); cudaGetSymbolAddress((void**)&predlo, g_predlo);
    cudaGetSymbolAddress((void**)&enchi, g_enchi);   cudaGetSymbolAddress((void**)&enclo, g_enclo);
    cudaGetSymbolAddress((void**)&zhi, g_zhi);       cudaGetSymbolAddress((void**)&zlo, g_zlo);
    cudaGetSymbolAddress((void**)&wenchi, g_wenchi); cudaGetSymbolAddress((void**)&wenclo, g_wenclo);
    cudaGetSymbolAddress((void**)&wpredhi, g_wpredhi); cudaGetSymbolAddress((void**)&wpredlo, g_wpredlo);
    cudaGetSymbolAddress((void**)&wouthi, g_wouthi); cudaGetSymbolAddress((void**)&woutlo, g_woutlo);

    const int SMEM0 = NSTAGE * 2 * TILEB;   // 81920
    const int SMEM1 = NSTAGE * 4 * TILEB;   // 163840
    cudaFuncSetAttribute((const void*)gemm_hmma<0, 1>,
                         cudaFuncAttributeMaxDynamicSharedMemorySize, SMEM0);
    cudaFuncSetAttribute((const void*)gemm_hmma<1, 0>,
                         cudaFuncAttributeMaxDynamicSharedMemorySize, SMEM1);

    // ---- fused prep (gather + all conversions + gate-interleave permute) ----
    prep_all<<<PB7, 256>>>(ids, (const float4*)emb, (const float4*)h0,
                           (const float4*)w_ih, (const float4*)w_hh,
                           (const float4*)enc, (const float4*)w_enc,
                           (const float4*)w_pred, (const float4*)w_out);

    const int WIH = 4 * H_ * H_;     // per-layer w_ih/w_hh elems
    const int BH  = B_ * H_;         // per-layer h slice elems

    dim3 blk(512);
    dim3 grdG(4 * H_ / 128, B_ / 128);   // 20 x 64

    // ---- layer 0: gates GEMM + fused cell -> h1[0], c1[0], h1s (fp16) ----
    gemm_hmma<0, 1><<<grdG, blk, SMEM0>>>(
        xh, nullptr, wih, nullptr, H_,
        h0h, nullptr, whh, nullptr, H_,
        b_ih, b_hh, nullptr, nullptr, nullptr, 0, 0,
        c0, h1f, c1f, h1s, nullptr, nullptr);

    // ---- layer 1: gates GEMM + fused cell -> h1[1], c1[1], pred hi/lo ----
    gemm_hmma<0, 1><<<grdG, blk, SMEM0>>>(
        h1s, nullptr, wih + WIH, nullptr, H_,
        h0h + BH, nullptr, whh + WIH, nullptr, H_,
        b_ih + 4 * H_, b_hh + 4 * H_, nullptr, nullptr, nullptr, 0, 0,
        c0 + BH, h1f + BH, c1f + BH, nullptr, predhi, predlo);

    // ---- joint: relu(enc*w_enc^T + pred*w_pred^T + b) -> z hi/lo (split) ----
    dim3 grdJ(J_ / 128, B_ / 128);       // 5 x 64
    gemm_hmma<1, 0><<<grdJ, blk, SMEM1>>>(
        enchi, enclo, wenchi, wenclo, D_,
        predhi, predlo, wpredhi, wpredlo, H_,
        b_enc, b_pred, nullptr, zhi, zlo, J_, 1,
        nullptr, nullptr, nullptr, nullptr, nullptr, nullptr);

    // ---- logits = z*w_out^T + b_out (split) ----
    dim3 grdO(V_ / 128, B_ / 128);       // 8 x 64
    gemm_hmma<1, 0><<<grdO, blk, SMEM1>>>(
        zhi, zlo, wouthi, woutlo, J_,
        nullptr, nullptr, nullptr, nullptr, 0,
        b_out, nullptr, logits, nullptr, nullptr, V_, 0,
        nullptr, nullptr, nullptr, nullptr, nullptr, nullptr);
}

// round 8
// speedup vs baseline: 1.3692x; 1.3671x over previous
#include <cuda_runtime.h>
#include <cuda_fp16.h>
#include <cstdint>

// ---------------- problem dims ----------------
#define B_ 8192
#define V_ 1024
#define E_ 640
#define H_ 640
#define L_ 2
#define D_ 512
#define J_ 640

// ---------------- GEMM smem layout ----------------
#define ROWB   80                    // bytes per smem row: 32 fp16 (64B) + 16B pad
#define TILEB  (128 * ROWB)          // one 128x32 fp16 tile = 10240 B

// ================= low-level helpers (base sm_100 ISA only) =================
__device__ __forceinline__ uint32_t smem_to_u32(const void* p) {
    uint32_t a;
    asm("{ .reg .u64 t; cvta.to.shared.u64 t, %1; cvt.u32.u64 %0, t; }"
        : "=r"(a) : "l"(p));
    return a;
}
__device__ __forceinline__ void cp_async16(uint32_t saddr, const void* gptr) {
    asm volatile("cp.async.cg.shared.global [%0], [%1], 16;"
                 :: "r"(saddr), "l"(gptr));
}
__device__ __forceinline__ void cp_commit() {
    asm volatile("cp.async.commit_group;");
}
template <int N>
__device__ __forceinline__ void cp_wait() {
    asm volatile("cp.async.wait_group %0;" :: "n"(N));
}
__device__ __forceinline__ void ldsm_x4(uint32_t* r, uint32_t addr) {
    asm volatile("ldmatrix.sync.aligned.m8n8.x4.shared.b16 {%0,%1,%2,%3}, [%4];"
                 : "=r"(r[0]), "=r"(r[1]), "=r"(r[2]), "=r"(r[3]) : "r"(addr));
}
__device__ __forceinline__ void mma_fp16(float* c, const uint32_t* a,
                                         uint32_t b0, uint32_t b1) {
    asm volatile(
        "mma.sync.aligned.m16n8k16.row.col.f32.f16.f16.f32 "
        "{%0,%1,%2,%3}, {%4,%5,%6,%7}, {%8,%9}, {%0,%1,%2,%3};"
        : "+f"(c[0]), "+f"(c[1]), "+f"(c[2]), "+f"(c[3])
        : "r"(a[0]), "r"(a[1]), "r"(a[2]), "r"(a[3]), "r"(b0), "r"(b1));
}

// ================= scratch (no allocations allowed) =================
__device__ float g_gates[B_ * 4 * H_];
// single-pass fp16 operands (gate GEMMs)
__device__ __align__(16) __half g_xh[B_ * E_];
__device__ __align__(16) __half g_h0h[L_ * B_ * H_];
__device__ __align__(16) __half g_h1s[B_ * H_];                 // layer-0 h1 (single)
__device__ __align__(16) __half g_wih[L_ * 4 * H_ * H_];
__device__ __align__(16) __half g_whh[L_ * 4 * H_ * H_];
// split fp16 operands (joint + output GEMMs)
__device__ __align__(16) __half g_predhi[B_ * H_], g_predlo[B_ * H_];
__device__ __align__(16) __half g_enchi[B_ * D_],  g_enclo[B_ * D_];
__device__ __align__(16) __half g_zhi[B_ * J_],    g_zlo[B_ * J_];
__device__ __align__(16) __half g_wenchi[J_ * D_], g_wenclo[J_ * D_];
__device__ __align__(16) __half g_wpredhi[J_ * H_], g_wpredlo[J_ * H_];
__device__ __align__(16) __half g_wouthi[V_ * J_],  g_woutlo[V_ * J_];

__device__ __forceinline__ void split1h(float v, __half& h, __half& l) {
    h = __float2half_rn(v);
    l = __float2half_rn(v - __half2float(h));
}
__device__ __forceinline__ float sigmoidf_(float x) {
    return 1.0f / (1.0f + expf(-x));
}

// ================= fused prep kernel (all conversions, one launch) ==========
// Segment sizes in float4 units (all multiples of 256):
//   s0 gather x      : B*E/4      = 1,310,720 -> 5120 blocks
//   s1 h0 conv       : L*B*H/4    = 2,621,440 -> 10240
//   s2 w_ih conv     : L*4H*H/4   =   819,200 -> 3200
//   s3 w_hh conv     : L*4H*H/4   =   819,200 -> 3200
//   s4 enc split     : B*D/4      = 1,048,576 -> 4096
//   s5 w_enc split   : J*D/4      =    81,920 -> 320
//   s6 w_pred split  : J*H/4      =   102,400 -> 400
//   s7 w_out split   : V*J/4      =   163,840 -> 640
#define PB0 5120
#define PB1 15360
#define PB2 18560
#define PB3 21760
#define PB4 25856
#define PB5 26176
#define PB6 26576
#define PB7 27216

__device__ __forceinline__ void conv_one(float4 v, __half2* out, size_t i) {
    out[2 * i]     = __floats2half2_rn(v.x, v.y);
    out[2 * i + 1] = __floats2half2_rn(v.z, v.w);
}
__device__ __forceinline__ void split_one(float4 v, __half2* hi, __half2* lo, size_t i) {
    __half hx, lx, hy, ly, hz, lz, hw, lw;
    split1h(v.x, hx, lx); split1h(v.y, hy, ly);
    split1h(v.z, hz, lz); split1h(v.w, hw, lw);
    hi[2 * i]     = __halves2half2(hx, hy);
    hi[2 * i + 1] = __halves2half2(hz, hw);
    lo[2 * i]     = __halves2half2(lx, ly);
    lo[2 * i + 1] = __halves2half2(lz, lw);
}

__global__ void prep_all(const int* __restrict__ ids, const float4* __restrict__ emb,
                         const float4* __restrict__ h0,
                         const float4* __restrict__ w_ih, const float4* __restrict__ w_hh,
                         const float4* __restrict__ enc, const float4* __restrict__ w_enc,
                         const float4* __restrict__ w_pred, const float4* __restrict__ w_out) {
    const int b = blockIdx.x;
    const int tid = threadIdx.x;
    if (b < PB0) {
        int i = b * 256 + tid;                       // over B_*(E_/4)
        int bb = i / (E_ / 4);
        int q  = i - bb * (E_ / 4);
        float4 v = emb[(size_t)ids[bb] * (E_ / 4) + q];
        conv_one(v, (__half2*)g_xh, i);
    } else if (b < PB1) {
        int i = (b - PB0) * 256 + tid;
        conv_one(h0[i], (__half2*)g_h0h, i);
    } else if (b < PB2) {
        int i = (b - PB1) * 256 + tid;
        conv_one(w_ih[i], (__half2*)g_wih, i);
    } else if (b < PB3) {
        int i = (b - PB2) * 256 + tid;
        conv_one(w_hh[i], (__half2*)g_whh, i);
    } else if (b < PB4) {
        int i = (b - PB3) * 256 + tid;
        split_one(enc[i], (__half2*)g_enchi, (__half2*)g_enclo, i);
    } else if (b < PB5) {
        int i = (b - PB4) * 256 + tid;
        split_one(w_enc[i], (__half2*)g_wenchi, (__half2*)g_wenclo, i);
    } else if (b < PB6) {
        int i = (b - PB5) * 256 + tid;
        split_one(w_pred[i], (__half2*)g_wpredhi, (__half2*)g_wpredlo, i);
    } else if (b < PB7) {
        int i = (b - PB6) * 256 + tid;
        split_one(w_out[i], (__half2*)g_wouthi, (__half2*)g_woutlo, i);
    }
}

// LSTM cell. If h1hi != nullptr -> write hi/lo fp16 split; else single fp16 to h1s.
__global__ void lstm_cell(const float* __restrict__ gates,
                          const float* __restrict__ c0,
                          float* __restrict__ h1f, float* __restrict__ c1f,
                          __half* __restrict__ h1s,
                          __half* __restrict__ h1hi, __half* __restrict__ h1lo) {
    int i = blockIdx.x * blockDim.x + threadIdx.x;   // over B_*H_
    if (i >= B_ * H_) return;
    int b = i / H_;
    int n = i - b * H_;
    const float* g = gates + (size_t)b * (4 * H_);
    float ig = sigmoidf_(g[n]);
    float fg = sigmoidf_(g[H_ + n]);
    float gg = tanhf(g[2 * H_ + n]);
    float og = sigmoidf_(g[3 * H_ + n]);
    float c  = fg * c0[i] + ig * gg;
    float h  = og * tanhf(c);
    c1f[i] = c;
    h1f[i] = h;
    if (h1hi) {
        __half hh, hl;
        split1h(h, hh, hl);
        h1hi[i] = hh;
        h1lo[i] = hl;
    } else {
        h1s[i] = __float2half_rn(h);
    }
}

// ================= fp16 HMMA GEMM =================
// SPLIT=0: single-pass fp16 (1 MMA/pair), 4-stage pipeline.
// SPLIT=1: 3-MMA hi/lo split (hi*hi + hi*lo + lo*hi), 2-stage pipeline.
// CTA tile 128x128, 256 threads = 8 warps (2 in M x 4 in N), warp tile 64x32.
// smem = 80 KB either way -> 2 CTAs/SM (the point of this round).
// If Chi != nullptr: write hi/lo fp16 split of C; else fp32 to Cf.
template <int SPLIT>
__global__ void __launch_bounds__(256, 2)
gemm_hmma(const __half* __restrict__ A1h, const __half* __restrict__ A1l,
          const __half* __restrict__ W1h, const __half* __restrict__ W1l, int K1,
          const __half* __restrict__ A2h, const __half* __restrict__ A2l,
          const __half* __restrict__ W2h, const __half* __restrict__ W2l, int K2,
          const float* __restrict__ b1, const float* __restrict__ b2,
          float* __restrict__ Cf,
          __half* __restrict__ Chi, __half* __restrict__ Clo,
          int ldc, int relu)
{
    constexpr int TILES  = SPLIT ? 4 : 2;
    constexpr int WOFF   = SPLIT ? 2 : 1;         // tile index of W_hi in stage
    constexpr int STAGEB = TILES * TILEB;
    constexpr int NST    = SPLIT ? 2 : 4;         // stages (both = 80 KB total)
    constexpr int PF     = NST - 1;               // prefetch distance

    extern __shared__ char smem[];
    const uint32_t sbase = smem_to_u32(smem);
    const int tid = threadIdx.x;
    const int wid = tid >> 5;
    const int lid = tid & 31;
    const int m0  = blockIdx.y * 128;
    const int n0  = blockIdx.x * 128;
    const int wm  = (wid & 1) * 64;     // warp M offset in tile
    const int wn  = (wid >> 1) * 32;    // warp N offset in tile

    float acc[4][4][4];
    #pragma unroll
    for (int i = 0; i < 4; i++)
        #pragma unroll
        for (int j = 0; j < 4; j++)
            #pragma unroll
            for (int k = 0; k < 4; k++) acc[i][j][k] = 0.f;

    const int nch1 = K1 / 32;
    const int nch  = nch1 + K2 / 32;

    auto load_chunk = [&](int c) {
        const __half* srcs[4];
        int kbase, Kc;
        if (c < nch1) {
            kbase = c * 32; Kc = K1;
            if (SPLIT) { srcs[0] = A1h; srcs[1] = A1l; srcs[2] = W1h; srcs[3] = W1l; }
            else       { srcs[0] = A1h; srcs[1] = W1h; }
        } else {
            kbase = (c - nch1) * 32; Kc = K2;
            if (SPLIT) { srcs[0] = A2h; srcs[1] = A2l; srcs[2] = W2h; srcs[3] = W2l; }
            else       { srcs[0] = A2h; srcs[1] = W2h; }
        }
        const uint32_t st = sbase + (uint32_t)(c % NST) * STAGEB;
        #pragma unroll
        for (int m = 0; m < TILES; ++m) {
            const int rb = (m < WOFF) ? m0 : n0;
            #pragma unroll
            for (int pp = 0; pp < 2; ++pp) {
                int idx = tid + pp * 256;           // 0..511
                int row = idx >> 2;                 // 0..127
                int cg  = idx & 3;                  // 16B group
                const void* g = srcs[m] + (size_t)(rb + row) * Kc + kbase + cg * 8;
                uint32_t s = st + m * TILEB + row * ROWB + cg * 16;
                cp_async16(s, g);
            }
        }
        cp_commit();
    };

    #pragma unroll
    for (int i = 0; i < PF; ++i) load_chunk(i);

    for (int c = 0; c < nch; ++c) {
        cp_wait<PF - 1>();         // chunk c resident
        __syncthreads();           // stage (c+PF)%NST free for reuse
        if (c + PF < nch) load_chunk(c + PF);

        const uint32_t st = sbase + (uint32_t)(c % NST) * STAGEB;
        #pragma unroll
        for (int ks = 0; ks < 2; ++ks) {
            const int kb = ks * 32;
            uint32_t ah[4][4], al[4][4];
            #pragma unroll
            for (int mf = 0; mf < 4; ++mf) {
                uint32_t addr = st + (wm + mf * 16 + (lid & 15)) * ROWB
                              + kb + ((lid >> 4) * 16);
                ldsm_x4(ah[mf], addr);
                if (SPLIT) ldsm_x4(al[mf], addr + TILEB);
            }
            uint32_t bh[2][4], bl[2][4];
            #pragma unroll
            for (int ng = 0; ng < 2; ++ng) {
                int nrow = wn + ng * 16 + ((lid >> 4) << 3) + (lid & 7);
                int kof  = ((lid >> 3) & 1) * 16;
                uint32_t addr = st + WOFF * TILEB + nrow * ROWB + kb + kof;
                ldsm_x4(bh[ng], addr);
                if (SPLIT) ldsm_x4(bl[ng], addr + TILEB);
            }
            #pragma unroll
            for (int mf = 0; mf < 4; ++mf)
                #pragma unroll
                for (int nf = 0; nf < 4; ++nf) {
                    const int ng = nf >> 1, hf = (nf & 1) * 2;
                    mma_fp16(acc[mf][nf], ah[mf], bh[ng][hf], bh[ng][hf + 1]);
                    if (SPLIT) {
                        mma_fp16(acc[mf][nf], ah[mf], bl[ng][hf], bl[ng][hf + 1]);
                        mma_fp16(acc[mf][nf], al[mf], bh[ng][hf], bh[ng][hf + 1]);
                    }
                }
        }
        __syncthreads();
    }

    // ---- epilogue ----
    const int g = lid >> 2;
    const int t = lid & 3;
    #pragma unroll
    for (int nf = 0; nf < 4; ++nf) {
        const int col = n0 + wn + nf * 8 + t * 2;
        float bb0 = b1[col],     bb1 = b1[col + 1];
        if (b2) { bb0 += b2[col]; bb1 += b2[col + 1]; }
        #pragma unroll
        for (int mf = 0; mf < 4; ++mf) {
            const int r0 = m0 + wm + mf * 16 + g;
            const int r1 = r0 + 8;
            float v00 = acc[mf][nf][0] + bb0;
            float v01 = acc[mf][nf][1] + bb1;
            float v10 = acc[mf][nf][2] + bb0;
            float v11 = acc[mf][nf][3] + bb1;
            if (relu) {
                v00 = fmaxf(v00, 0.f); v01 = fmaxf(v01, 0.f);
                v10 = fmaxf(v10, 0.f); v11 = fmaxf(v11, 0.f);
            }
            if (Chi) {
                __half h0b, l0b, h1b, l1b;
                split1h(v00, h0b, l0b); split1h(v01, h1b, l1b);
                *reinterpret_cast<__half2*>(Chi + (size_t)r0 * ldc + col) = __halves2half2(h0b, h1b);
                *reinterpret_cast<__half2*>(Clo + (size_t)r0 * ldc + col) = __halves2half2(l0b, l1b);
                split1h(v10, h0b, l0b); split1h(v11, h1b, l1b);
                *reinterpret_cast<__half2*>(Chi + (size_t)r1 * ldc + col) = __halves2half2(h0b, h1b);
                *reinterpret_cast<__half2*>(Clo + (size_t)r1 * ldc + col) = __halves2half2(l0b, l1b);
            } else {
                *reinterpret_cast<float2*>(Cf + (size_t)r0 * ldc + col) = make_float2(v00, v01);
                *reinterpret_cast<float2*>(Cf + (size_t)r1 * ldc + col) = make_float2(v10, v11);
            }
        }
    }
}

// ================= launch =================
extern "C" void kernel_launch(void* const* d_in, const int* in_sizes, int n_in,
                              void* d_out, int out_size) {
    const int*   ids    = (const int*)  d_in[0];
    const float* h0     = (const float*)d_in[1];
    const float* c0     = (const float*)d_in[2];
    const float* enc    = (const float*)d_in[3];
    const float* emb    = (const float*)d_in[4];
    const float* w_ih   = (const float*)d_in[5];
    const float* w_hh   = (const float*)d_in[6];
    const float* b_ih   = (const float*)d_in[7];
    const float* b_hh   = (const float*)d_in[8];
    const float* w_enc  = (const float*)d_in[9];
    const float* b_enc  = (const float*)d_in[10];
    const float* w_pred = (const float*)d_in[11];
    const float* b_pred = (const float*)d_in[12];
    const float* w_out  = (const float*)d_in[13];
    const float* b_out  = (const float*)d_in[14];

    float* out    = (float*)d_out;
    float* logits = out;                                 // (B, V)
    float* h1f    = out + (size_t)B_ * V_;               // (L, B, H)
    float* c1f    = h1f + (size_t)L_ * B_ * H_;          // (L, B, H)

    float* gates;
    __half *xh, *h0h, *h1s, *wih, *whh;
    __half *predhi, *predlo, *enchi, *enclo, *zhi, *zlo;
    __half *wenchi, *wenclo, *wpredhi, *wpredlo, *wouthi, *woutlo;
    cudaGetSymbolAddress((void**)&gates, g_gates);
    cudaGetSymbolAddress((void**)&xh,  g_xh);
    cudaGetSymbolAddress((void**)&h0h, g_h0h);
    cudaGetSymbolAddress((void**)&h1s, g_h1s);
    cudaGetSymbolAddress((void**)&wih, g_wih);
    cudaGetSymbolAddress((void**)&whh, g_whh);
    cudaGetSymbolAddress((void**)&predhi, g_predhi); cudaGetSymbolAddress((void**)&predlo, g_predlo);
    cudaGetSymbolAddress((void**)&enchi, g_enchi);   cudaGetSymbolAddress((void**)&enclo, g_enclo);
    cudaGetSymbolAddress((void**)&zhi, g_zhi);       cudaGetSymbolAddress((void**)&zlo, g_zlo);
    cudaGetSymbolAddress((void**)&wenchi, g_wenchi); cudaGetSymbolAddress((void**)&wenclo, g_wenclo);
    cudaGetSymbolAddress((void**)&wpredhi, g_wpredhi); cudaGetSymbolAddress((void**)&wpredlo, g_wpredlo);
    cudaGetSymbolAddress((void**)&wouthi, g_wouthi); cudaGetSymbolAddress((void**)&woutlo, g_woutlo);

    const int SMEMG = 8 * TILEB;            // 81920 both variants
    cudaFuncSetAttribute((const void*)gemm_hmma<0>,
                         cudaFuncAttributeMaxDynamicSharedMemorySize, SMEMG);
    cudaFuncSetAttribute((const void*)gemm_hmma<1>,
                         cudaFuncAttributeMaxDynamicSharedMemorySize, SMEMG);

    auto grid1d = [](long n) { return (int)((n + 255) / 256); };

    // ---- fused prep (gather + all conversions) ----
    prep_all<<<PB7, 256>>>(ids, (const float4*)emb, (const float4*)h0,
                           (const float4*)w_ih, (const float4*)w_hh,
                           (const float4*)enc, (const float4*)w_enc,
                           (const float4*)w_pred, (const float4*)w_out);

    const int WIH = 4 * H_ * H_;     // per-layer w_ih/w_hh elems
    const int BH  = B_ * H_;         // per-layer h slice elems

    dim3 blk(256);
    dim3 grdG(4 * H_ / 128, B_ / 128);   // 20 x 64

    // ---- layer 0 gates (single-pass fp16) ----
    gemm_hmma<0><<<grdG, blk, SMEMG>>>(
        xh, nullptr, wih, nullptr, H_,
        h0h, nullptr, whh, nullptr, H_,
        b_ih, b_hh, gates, nullptr, nullptr, 4 * H_, 0);
    lstm_cell<<<grid1d((long)BH), 256>>>(gates, c0, h1f, c1f, h1s, nullptr, nullptr);

    // ---- layer 1 gates ----
    gemm_hmma<0><<<grdG, blk, SMEMG>>>(
        h1s, nullptr, wih + WIH, nullptr, H_,
        h0h + BH, nullptr, whh + WIH, nullptr, H_,
        b_ih + 4 * H_, b_hh + 4 * H_, gates, nullptr, nullptr, 4 * H_, 0);
    lstm_cell<<<grid1d((long)BH), 256>>>(gates, c0 + BH, h1f + BH, c1f + BH,
                                         nullptr, predhi, predlo);

    // ---- joint: relu(enc*w_enc^T + pred*w_pred^T + b) -> z hi/lo (split) ----
    dim3 grdJ(J_ / 128, B_ / 128);       // 5 x 64
    gemm_hmma<1><<<grdJ, blk, SMEMG>>>(
        enchi, enclo, wenchi, wenclo, D_,
        predhi, predlo, wpredhi, wpredlo, H_,
        b_enc, b_pred, nullptr, zhi, zlo, J_, 1);

    // ---- logits = z*w_out^T + b_out (split) ----
    dim3 grdO(V_ / 128, B_ / 128);       // 8 x 64
    gemm_hmma<1><<<grdO, blk, SMEMG>>>(
        zhi, zlo, wouthi, woutlo, J_,
        nullptr, nullptr, nullptr, nullptr, 0,
        b_out, nullptr, logits, nullptr, nullptr, V_, 0);
}

// round 11
// speedup vs baseline: 1.4510x; 1.0597x over previous
#include <cuda_runtime.h>
#include <cuda_fp16.h>
#include <cstdint>

// ---------------- problem dims ----------------
#define B_ 8192
#define V_ 1024
#define E_ 640
#define H_ 640
#define L_ 2
#define D_ 512
#define J_ 640

// ================= low-level helpers (base sm_100 ISA only) =================
__device__ __forceinline__ uint32_t smem_to_u32(const void* p) {
    uint32_t a;
    asm("{ .reg .u64 t; cvta.to.shared.u64 t, %1; cvt.u32.u64 %0, t; }"
        : "=r"(a) : "l"(p));
    return a;
}
__device__ __forceinline__ void cp_async16(uint32_t saddr, const void* gptr) {
    asm volatile("cp.async.cg.shared.global [%0], [%1], 16;"
                 :: "r"(saddr), "l"(gptr));
}
__device__ __forceinline__ void cp_commit() {
    asm volatile("cp.async.commit_group;");
}
template <int N>
__device__ __forceinline__ void cp_wait() {
    asm volatile("cp.async.wait_group %0;" :: "n"(N));
}
__device__ __forceinline__ void ldsm_x4(uint32_t* r, uint32_t addr) {
    asm volatile("ldmatrix.sync.aligned.m8n8.x4.shared.b16 {%0,%1,%2,%3}, [%4];"
                 : "=r"(r[0]), "=r"(r[1]), "=r"(r[2]), "=r"(r[3]) : "r"(addr));
}
__device__ __forceinline__ void mma_fp16(float* c, const uint32_t* a,
                                         uint32_t b0, uint32_t b1) {
    asm volatile(
        "mma.sync.aligned.m16n8k16.row.col.f32.f16.f16.f32 "
        "{%0,%1,%2,%3}, {%4,%5,%6,%7}, {%8,%9}, {%0,%1,%2,%3};"
        : "+f"(c[0]), "+f"(c[1]), "+f"(c[2]), "+f"(c[3])
        : "r"(a[0]), "r"(a[1]), "r"(a[2]), "r"(a[3]), "r"(b0), "r"(b1));
}

// ================= scratch (no allocations allowed) =================
__device__ float g_gates[B_ * 4 * H_];
// single-pass fp16 operands (gate GEMMs)
__device__ __align__(16) __half g_xh[B_ * E_];
__device__ __align__(16) __half g_h0h[L_ * B_ * H_];
__device__ __align__(16) __half g_h1s[B_ * H_];                 // layer-0 h1 (single)
__device__ __align__(16) __half g_wih[L_ * 4 * H_ * H_];
__device__ __align__(16) __half g_whh[L_ * 4 * H_ * H_];
// split fp16 operands (joint + output GEMMs)
__device__ __align__(16) __half g_predhi[B_ * H_], g_predlo[B_ * H_];
__device__ __align__(16) __half g_enchi[B_ * D_],  g_enclo[B_ * D_];
__device__ __align__(16) __half g_zhi[B_ * J_],    g_zlo[B_ * J_];
__device__ __align__(16) __half g_wenchi[J_ * D_], g_wenclo[J_ * D_];
__device__ __align__(16) __half g_wpredhi[J_ * H_], g_wpredlo[J_ * H_];
__device__ __align__(16) __half g_wouthi[V_ * J_],  g_woutlo[V_ * J_];

__device__ __forceinline__ void split1h(float v, __half& h, __half& l) {
    h = __float2half_rn(v);
    l = __float2half_rn(v - __half2float(h));
}
__device__ __forceinline__ float sigmoidf_(float x) {
    return 1.0f / (1.0f + expf(-x));
}

// ================= fused prep kernel (all conversions, one launch) ==========
#define PB0 5120
#define PB1 15360
#define PB2 18560
#define PB3 21760
#define PB4 25856
#define PB5 26176
#define PB6 26576
#define PB7 27216

__device__ __forceinline__ void conv_one(float4 v, __half2* out, size_t i) {
    out[2 * i]     = __floats2half2_rn(v.x, v.y);
    out[2 * i + 1] = __floats2half2_rn(v.z, v.w);
}
__device__ __forceinline__ void split_one(float4 v, __half2* hi, __half2* lo, size_t i) {
    __half hx, lx, hy, ly, hz, lz, hw, lw;
    split1h(v.x, hx, lx); split1h(v.y, hy, ly);
    split1h(v.z, hz, lz); split1h(v.w, hw, lw);
    hi[2 * i]     = __halves2half2(hx, hy);
    hi[2 * i + 1] = __halves2half2(hz, hw);
    lo[2 * i]     = __halves2half2(lx, ly);
    lo[2 * i + 1] = __halves2half2(lz, lw);
}

__global__ void prep_all(const int* __restrict__ ids, const float4* __restrict__ emb,
                         const float4* __restrict__ h0,
                         const float4* __restrict__ w_ih, const float4* __restrict__ w_hh,
                         const float4* __restrict__ enc, const float4* __restrict__ w_enc,
                         const float4* __restrict__ w_pred, const float4* __restrict__ w_out) {
    const int b = blockIdx.x;
    const int tid = threadIdx.x;
    if (b < PB0) {
        int i = b * 256 + tid;                       // over B_*(E_/4)
        int bb = i / (E_ / 4);
        int q  = i - bb * (E_ / 4);
        float4 v = emb[(size_t)ids[bb] * (E_ / 4) + q];
        conv_one(v, (__half2*)g_xh, i);
    } else if (b < PB1) {
        int i = (b - PB0) * 256 + tid;
        conv_one(h0[i], (__half2*)g_h0h, i);
    } else if (b < PB2) {
        int i = (b - PB1) * 256 + tid;
        conv_one(w_ih[i], (__half2*)g_wih, i);
    } else if (b < PB3) {
        int i = (b - PB2) * 256 + tid;
        conv_one(w_hh[i], (__half2*)g_whh, i);
    } else if (b < PB4) {
        int i = (b - PB3) * 256 + tid;
        split_one(enc[i], (__half2*)g_enchi, (__half2*)g_enclo, i);
    } else if (b < PB5) {
        int i = (b - PB4) * 256 + tid;
        split_one(w_enc[i], (__half2*)g_wenchi, (__half2*)g_wenclo, i);
    } else if (b < PB6) {
        int i = (b - PB5) * 256 + tid;
        split_one(w_pred[i], (__half2*)g_wpredhi, (__half2*)g_wpredlo, i);
    } else if (b < PB7) {
        int i = (b - PB6) * 256 + tid;
        split_one(w_out[i], (__half2*)g_wouthi, (__half2*)g_woutlo, i);
    }
}

// LSTM cell. If h1hi != nullptr -> write hi/lo fp16 split; else single fp16 to h1s.
__global__ void lstm_cell(const float* __restrict__ gates,
                          const float* __restrict__ c0,
                          float* __restrict__ h1f, float* __restrict__ c1f,
                          __half* __restrict__ h1s,
                          __half* __restrict__ h1hi, __half* __restrict__ h1lo) {
    int i = blockIdx.x * blockDim.x + threadIdx.x;   // over B_*H_
    if (i >= B_ * H_) return;
    int b = i / H_;
    int n = i - b * H_;
    const float* g = gates + (size_t)b * (4 * H_);
    float ig = sigmoidf_(g[n]);
    float fg = sigmoidf_(g[H_ + n]);
    float gg = tanhf(g[2 * H_ + n]);
    float og = sigmoidf_(g[3 * H_ + n]);
    float c  = fg * c0[i] + ig * gg;
    float h  = og * tanhf(c);
    c1f[i] = c;
    h1f[i] = h;
    if (h1hi) {
        __half hh, hl;
        split1h(h, hh, hl);
        h1hi[i] = hh;
        h1lo[i] = hl;
    } else {
        h1s[i] = __float2half_rn(h);
    }
}

// ================= fp16 HMMA GEMM =================
// SPLIT=0: single-pass fp16, BK=64 chunks, DOUBLE-buffered (36 KB/stage,
//          73.7 KB smem -> 2 CTAs/SM with headroom). Halved sync cadence.
// SPLIT=1: 3-MMA hi/lo split, BK=32 chunks, 2-stage (80 KB -> 2 CTAs/SM).
// CTA tile 128x128, 256 threads = 8 warps (2 M x 4 N), warp tile 64x32.
// If Chi != nullptr: write hi/lo fp16 split of C; else fp32 to Cf.
template <int SPLIT>
__global__ void __launch_bounds__(256, 2)
gemm_hmma(const __half* __restrict__ A1h, const __half* __restrict__ A1l,
          const __half* __restrict__ W1h, const __half* __restrict__ W1l, int K1,
          const __half* __restrict__ A2h, const __half* __restrict__ A2l,
          const __half* __restrict__ W2h, const __half* __restrict__ W2l, int K2,
          const float* __restrict__ b1, const float* __restrict__ b2,
          float* __restrict__ Cf,
          __half* __restrict__ Chi, __half* __restrict__ Clo,
          int ldc, int relu)
{
    constexpr int BKC    = SPLIT ? 32 : 64;            // K per chunk
    constexpr int ROWB   = SPLIT ? 80 : 144;           // row bytes (data + 16B pad)
    constexpr int TILEB  = 128 * ROWB;
    constexpr int TILES  = SPLIT ? 4 : 2;
    constexpr int WOFF   = SPLIT ? 2 : 1;              // tile index of W_hi
    constexpr int STAGEB = TILES * TILEB;
    constexpr int NKS    = BKC / 16;                   // k-steps per chunk
    constexpr int GRP    = BKC / 8;                    // 16B groups per row
    constexpr int PP     = 128 * GRP / 256;            // cp iters per tile

    extern __shared__ char smem[];
    const uint32_t sbase = smem_to_u32(smem);
    const int tid = threadIdx.x;
    const int wid = tid >> 5;
    const int lid = tid & 31;
    const int m0  = blockIdx.y * 128;
    const int n0  = blockIdx.x * 128;
    const int wm  = (wid & 1) * 64;     // warp M offset in tile
    const int wn  = (wid >> 1) * 32;    // warp N offset in tile

    float acc[4][4][4];
    #pragma unroll
    for (int i = 0; i < 4; i++)
        #pragma unroll
        for (int j = 0; j < 4; j++)
            #pragma unroll
            for (int k = 0; k < 4; k++) acc[i][j][k] = 0.f;

    const int nch1 = K1 / BKC;
    const int nch  = nch1 + K2 / BKC;

    auto load_chunk = [&](int c) {
        const __half* srcs[4];
        int kbase, Kc;
        if (c < nch1) {
            kbase = c * BKC; Kc = K1;
            if (SPLIT) { srcs[0] = A1h; srcs[1] = A1l; srcs[2] = W1h; srcs[3] = W1l; }
            else       { srcs[0] = A1h; srcs[1] = W1h; }
        } else {
            kbase = (c - nch1) * BKC; Kc = K2;
            if (SPLIT) { srcs[0] = A2h; srcs[1] = A2l; srcs[2] = W2h; srcs[3] = W2l; }
            else       { srcs[0] = A2h; srcs[1] = W2h; }
        }
        const uint32_t st = sbase + (uint32_t)(c & 1) * STAGEB;
        #pragma unroll
        for (int m = 0; m < TILES; ++m) {
            const int rb = (m < WOFF) ? m0 : n0;
            #pragma unroll
            for (int pp = 0; pp < PP; ++pp) {
                int idx = tid + pp * 256;
                int row = idx / GRP;
                int cg  = idx % GRP;
                const void* g = srcs[m] + (size_t)(rb + row) * Kc + kbase + cg * 8;
                uint32_t s = st + m * TILEB + row * ROWB + cg * 16;
                cp_async16(s, g);
            }
        }
        cp_commit();
    };

    load_chunk(0);

    for (int c = 0; c < nch; ++c) {
        cp_wait<0>();              // chunk c resident (and any previous)
        __syncthreads();           // stage (c+1)&1 free for reuse
        if (c + 1 < nch) load_chunk(c + 1);

        const uint32_t st = sbase + (uint32_t)(c & 1) * STAGEB;
        #pragma unroll
        for (int ks = 0; ks < NKS; ++ks) {
            const int kb = ks * 32;
            uint32_t ah[4][4], al[4][4];
            #pragma unroll
            for (int mf = 0; mf < 4; ++mf) {
                uint32_t addr = st + (wm + mf * 16 + (lid & 15)) * ROWB
                              + kb + ((lid >> 4) * 16);
                ldsm_x4(ah[mf], addr);
                if (SPLIT) ldsm_x4(al[mf], addr + TILEB);
            }
            uint32_t bh[2][4], bl[2][4];
            #pragma unroll
            for (int ng = 0; ng < 2; ++ng) {
                int nrow = wn + ng * 16 + ((lid >> 4) << 3) + (lid & 7);
                int kof  = ((lid >> 3) & 1) * 16;
                uint32_t addr = st + WOFF * TILEB + nrow * ROWB + kb + kof;
                ldsm_x4(bh[ng], addr);
                if (SPLIT) ldsm_x4(bl[ng], addr + TILEB);
            }
            #pragma unroll
            for (int mf = 0; mf < 4; ++mf)
                #pragma unroll
                for (int nf = 0; nf < 4; ++nf) {
                    const int ng = nf >> 1, hf = (nf & 1) * 2;
                    mma_fp16(acc[mf][nf], ah[mf], bh[ng][hf], bh[ng][hf + 1]);
                    if (SPLIT) {
                        mma_fp16(acc[mf][nf], ah[mf], bl[ng][hf], bl[ng][hf + 1]);
                        mma_fp16(acc[mf][nf], al[mf], bh[ng][hf], bh[ng][hf + 1]);
                    }
                }
        }
        __syncthreads();
    }

    // ---- epilogue ----
    const int g = lid >> 2;
    const int t = lid & 3;
    #pragma unroll
    for (int nf = 0; nf < 4; ++nf) {
        const int col = n0 + wn + nf * 8 + t * 2;
        float bb0 = b1[col],     bb1 = b1[col + 1];
        if (b2) { bb0 += b2[col]; bb1 += b2[col + 1]; }
        #pragma unroll
        for (int mf = 0; mf < 4; ++mf) {
            const int r0 = m0 + wm + mf * 16 + g;
            const int r1 = r0 + 8;
            float v00 = acc[mf][nf][0] + bb0;
            float v01 = acc[mf][nf][1] + bb1;
            float v10 = acc[mf][nf][2] + bb0;
            float v11 = acc[mf][nf][3] + bb1;
            if (relu) {
                v00 = fmaxf(v00, 0.f); v01 = fmaxf(v01, 0.f);
                v10 = fmaxf(v10, 0.f); v11 = fmaxf(v11, 0.f);
            }
            if (Chi) {
                __half h0b, l0b, h1b, l1b;
                split1h(v00, h0b, l0b); split1h(v01, h1b, l1b);
                *reinterpret_cast<__half2*>(Chi + (size_t)r0 * ldc + col) = __halves2half2(h0b, h1b);
                *reinterpret_cast<__half2*>(Clo + (size_t)r0 * ldc + col) = __halves2half2(l0b, l1b);
                split1h(v10, h0b, l0b); split1h(v11, h1b, l1b);
                *reinterpret_cast<__half2*>(Chi + (size_t)r1 * ldc + col) = __halves2half2(h0b, h1b);
                *reinterpret_cast<__half2*>(Clo + (size_t)r1 * ldc + col) = __halves2half2(l0b, l1b);
            } else {
                *reinterpret_cast<float2*>(Cf + (size_t)r0 * ldc + col) = make_float2(v00, v01);
                *reinterpret_cast<float2*>(Cf + (size_t)r1 * ldc + col) = make_float2(v10, v11);
            }
        }
    }
}

// ================= launch =================
extern "C" void kernel_launch(void* const* d_in, const int* in_sizes, int n_in,
                              void* d_out, int out_size) {
    const int*   ids    = (const int*)  d_in[0];
    const float* h0     = (const float*)d_in[1];
    const float* c0     = (const float*)d_in[2];
    const float* enc    = (const float*)d_in[3];
    const float* emb    = (const float*)d_in[4];
    const float* w_ih   = (const float*)d_in[5];
    const float* w_hh   = (const float*)d_in[6];
    const float* b_ih   = (const float*)d_in[7];
    const float* b_hh   = (const float*)d_in[8];
    const float* w_enc  = (const float*)d_in[9];
    const float* b_enc  = (const float*)d_in[10];
    const float* w_pred = (const float*)d_in[11];
    const float* b_pred = (const float*)d_in[12];
    const float* w_out  = (const float*)d_in[13];
    const float* b_out  = (const float*)d_in[14];

    float* out    = (float*)d_out;
    float* logits = out;                                 // (B, V)
    float* h1f    = out + (size_t)B_ * V_;               // (L, B, H)
    float* c1f    = h1f + (size_t)L_ * B_ * H_;          // (L, B, H)

    float* gates;
    __half *xh, *h0h, *h1s, *wih, *whh;
    __half *predhi, *predlo, *enchi, *enclo, *zhi, *zlo;
    __half *wenchi, *wenclo, *wpredhi, *wpredlo, *wouthi, *woutlo;
    cudaGetSymbolAddress((void**)&gates, g_gates);
    cudaGetSymbolAddress((void**)&xh,  g_xh);
    cudaGetSymbolAddress((void**)&h0h, g_h0h);
    cudaGetSymbolAddress((void**)&h1s, g_h1s);
    cudaGetSymbolAddress((void**)&wih, g_wih);
    cudaGetSymbolAddress((void**)&whh, g_whh);
    cudaGetSymbolAddress((void**)&predhi, g_predhi); cudaGetSymbolAddress((void**)&predlo, g_predlo);
    cudaGetSymbolAddress((void**)&enchi, g_enchi);   cudaGetSymbolAddress((void**)&enclo, g_enclo);
    cudaGetSymbolAddress((void**)&zhi, g_zhi);       cudaGetSymbolAddress((void**)&zlo, g_zlo);
    cudaGetSymbolAddress((void**)&wenchi, g_wenchi); cudaGetSymbolAddress((void**)&wenclo, g_wenclo);
    cudaGetSymbolAddress((void**)&wpredhi, g_wpredhi); cudaGetSymbolAddress((void**)&wpredlo, g_wpredlo);
    cudaGetSymbolAddress((void**)&wouthi, g_wouthi); cudaGetSymbolAddress((void**)&woutlo, g_woutlo);

    const int SMEM0 = 2 * 2 * 128 * 144;    // 73728 (BK=64, double buffer)
    const int SMEM1 = 2 * 4 * 128 * 80;     // 81920 (BK=32, double buffer)
    cudaFuncSetAttribute((const void*)gemm_hmma<0>,
                         cudaFuncAttributeMaxDynamicSharedMemorySize, SMEM0);
    cudaFuncSetAttribute((const void*)gemm_hmma<1>,
                         cudaFuncAttributeMaxDynamicSharedMemorySize, SMEM1);

    auto grid1d = [](long n) { return (int)((n + 255) / 256); };

    // ---- fused prep (gather + all conversions) ----
    prep_all<<<PB7, 256>>>(ids, (const float4*)emb, (const float4*)h0,
                           (const float4*)w_ih, (const float4*)w_hh,
                           (const float4*)enc, (const float4*)w_enc,
                           (const float4*)w_pred, (const float4*)w_out);

    const int WIH = 4 * H_ * H_;     // per-layer w_ih/w_hh elems
    const int BH  = B_ * H_;         // per-layer h slice elems

    dim3 blk(256);
    dim3 grdG(4 * H_ / 128, B_ / 128);   // 20 x 64

    // ---- layer 0 gates (single-pass fp16, BK=64) ----
    gemm_hmma<0><<<grdG, blk, SMEM0>>>(
        xh, nullptr, wih, nullptr, H_,
        h0h, nullptr, whh, nullptr, H_,
        b_ih, b_hh, gates, nullptr, nullptr, 4 * H_, 0);
    lstm_cell<<<grid1d((long)BH), 256>>>(gates, c0, h1f, c1f, h1s, nullptr, nullptr);

    // ---- layer 1 gates ----
    gemm_hmma<0><<<grdG, blk, SMEM0>>>(
        h1s, nullptr, wih + WIH, nullptr, H_,
        h0h + BH, nullptr, whh + WIH, nullptr, H_,
        b_ih + 4 * H_, b_hh + 4 * H_, gates, nullptr, nullptr, 4 * H_, 0);
    lstm_cell<<<grid1d((long)BH), 256>>>(gates, c0 + BH, h1f + BH, c1f + BH,
                                         nullptr, predhi, predlo);

    // ---- joint: relu(enc*w_enc^T + pred*w_pred^T + b) -> z hi/lo (split) ----
    dim3 grdJ(J_ / 128, B_ / 128);       // 5 x 64
    gemm_hmma<1><<<grdJ, blk, SMEM1>>>(
        enchi, enclo, wenchi, wenclo, D_,
        predhi, predlo, wpredhi, wpredlo, H_,
        b_enc, b_pred, nullptr, zhi, zlo, J_, 1);

    // ---- logits = z*w_out^T + b_out (split) ----
    dim3 grdO(V_ / 128, B_ / 128);       // 8 x 64
    gemm_hmma<1><<<grdO, blk, SMEM1>>>(
        zhi, zlo, wouthi, woutlo, J_,
        nullptr, nullptr, nullptr, nullptr, 0,
        b_out, nullptr, logits, nullptr, nullptr, V_, 0);
}